// round 13
// baseline (speedup 1.0000x reference)
#include <cuda_runtime.h>
#include <cuda_bf16.h>
#include <math.h>
#include <stdint.h>

#define BB 2
#define TT 12
#define CC 128
#define NHEAD 4
#define DHH 32
#define NPIX 1024
#define NT (BB*TT)
#define IMG (CC*NPIX)
#define TOT (NT*IMG)

#define YTOT (NT*1156*256)
#define WPERSHCH 12288
#define WPERCONV (36*WPERSHCH)
#define WPTOT (15*WPERCONV)

// ---- scratch ----
__device__ float g_cur[TOT];
__device__ float g_v[TOT];
__device__ float g_ak[BB*NHEAD*TT*NPIX];
__device__ float g_ws[BB*CC*NPIX];
__device__ float g_att[TOT];
__device__ float g_ff1[TOT];
__device__ float g_ff2[TOT];
__device__ __nv_bfloat16 g_Y[YTOT];
__device__ __nv_bfloat16 g_Wp[WPTOT];

// ---- smem layout for conv kernel (dynamic) ----
#define BBUF 48960                 // 340 pixel-rows * 144B
#define V1OFF 9216                 // var0: 64 rows * 144B
#define WBUF 14336                 // + var1: 64 rows * 80B
#define WOFF (2*BBUF)              // 97920
#define CSMEM (2*BBUF + 3*WBUF)    // 140928

#define AKSMEM (32*1156*4 + 288*4) // 149120

// ---- PTX helpers ----
__device__ __forceinline__ void cp16(void* d, const void* s) {
    unsigned a = (unsigned)__cvta_generic_to_shared(d);
    asm volatile("cp.async.cg.shared.global [%0], [%1], 16;" :: "r"(a), "l"(s));
}
__device__ __forceinline__ void cp_commit() { asm volatile("cp.async.commit_group;" ::: "memory"); }
__device__ __forceinline__ void cp_wait1()  { asm volatile("cp.async.wait_group 1;" ::: "memory"); }

__device__ __forceinline__ void ldsm4(uint32_t* r, uint32_t a) {
    asm volatile("ldmatrix.sync.aligned.m8n8.x4.shared.b16 {%0,%1,%2,%3}, [%4];"
        : "=r"(r[0]), "=r"(r[1]), "=r"(r[2]), "=r"(r[3]) : "r"(a));
}
__device__ __forceinline__ void mma16816(float* d, const uint32_t* a, const uint32_t* b) {
    asm volatile("mma.sync.aligned.m16n8k16.row.col.f32.bf16.bf16.f32 "
        "{%0,%1,%2,%3}, {%4,%5,%6,%7}, {%8,%9}, {%0,%1,%2,%3};"
        : "+f"(d[0]), "+f"(d[1]), "+f"(d[2]), "+f"(d[3])
        : "r"(a[0]), "r"(a[1]), "r"(a[2]), "r"(a[3]), "r"(b[0]), "r"(b[1]));
}

// ============================================================
// weight prep: var0 (K64) = [w_hi|w_hi]; var1 (K32) = [w_lo]
// kv conv expanded block-diagonal into dense 128x128.
// ============================================================
__global__ __launch_bounds__(256)
void wprep_kernel(const float* __restrict__ kvw, const float* __restrict__ ff1w,
                  const float* __restrict__ ff2w, __nv_bfloat16* __restrict__ Wp)
{
    int idx = blockIdx.x * 256 + threadIdx.x;
    if (idx >= WPTOT) return;
    int conv = idx / WPERCONV;
    int o    = idx - conv * WPERCONV;
    int t    = o / WPERSHCH;
    int r    = o - t * WPERSHCH;
    int sh = t >> 2, ch = t & 3;
    int l = conv / 3, type = conv - l * 3;
    int kr = sh / 3, kc = sh - kr * 3;
    int var, co, k;
    if (r < 8192) { var = 0; co = r >> 6; k = r & 63; }
    else          { var = 1; int r2 = r - 8192; co = r2 >> 5; k = r2 & 31; }
    int cil = k & 31;
    float w;
    if (type == 0) {
        w = ((co >> 5) == ch)
          ? kvw[((((size_t)l * 4 + ch) * 32 + (co & 31)) * 32 + cil) * 9 + kr * 3 + kc]
          : 0.f;
    } else {
        const float* W = (type == 1) ? ff1w : ff2w;
        w = W[(((size_t)l * 128 + co) * 128 + ch * 32 + cil) * 9 + kr * 3 + kc];
    }
    __nv_bfloat16 hi = __float2bfloat16(w);
    Wp[idx] = (var == 0) ? hi : __float2bfloat16(w - __bfloat162float(hi));
}

__global__ __launch_bounds__(256)
void yzero_kernel(unsigned* __restrict__ Y32)
{
    size_t i = (size_t)blockIdx.x * 256 + threadIdx.x;
    if (i < YTOT / 2) Y32[i] = 0u;
}

// ============================================================
// planar fp32 -> Y split (coalesced); WS: input = x + ws, also writes att
// ============================================================
template<bool WS>
__global__ __launch_bounds__(256)
void prep_kernel(const float* __restrict__ x, const float* __restrict__ ws,
                 float* __restrict__ att, __nv_bfloat16* __restrict__ Y)
{
    __shared__ float sm[128 * 33];
    const int img = blockIdx.x >> 5;
    const int row = blockIdx.x & 31;
    const int tid = threadIdx.x;
    const int c   = tid & 31;
    const int ci0 = tid >> 5;
    const int b   = img / TT;
    const float* xp = x + (size_t)img * IMG + row * 32;
    #pragma unroll
    for (int k = 0; k < 16; ++k) {
        int ci = ci0 * 16 + k;
        float val = xp[(size_t)ci * NPIX + c];
        if (WS) {
            val += ws[((size_t)b * CC + ci) * NPIX + row * 32 + c];
            att[(size_t)img * IMG + (size_t)ci * NPIX + row * 32 + c] = val;
        }
        sm[ci * 33 + c] = val;
    }
    __syncthreads();

    unsigned* out32 = reinterpret_cast<unsigned*>(Y + ((size_t)img * 1156 + (row + 1) * 34 + 1) * 256);
    const int q  = tid & 127;
    const int ph = tid >> 7;
    #pragma unroll
    for (int p = 0; p < 16; ++p) {
        int c2 = p * 2 + ph;
        unsigned pk = 0;
        #pragma unroll
        for (int half = 0; half < 2; ++half) {
            int e  = q * 2 + half;
            int ch = e >> 6, r6 = e & 63;
            float xv = sm[(ch * 32 + (r6 & 31)) * 33 + c2];
            __nv_bfloat16 hi = __float2bfloat16(xv);
            __nv_bfloat16 v  = (r6 >= 32) ? __float2bfloat16(xv - __bfloat162float(hi)) : hi;
            pk |= ((unsigned)__bfloat16_as_ushort(v)) << (16 * half);
        }
        out32[(size_t)c2 * 128 + q] = pk;
    }
}

// ============================================================
// conv via mma.sync: D[64co x 256pix] per CTA (co-split grid 192),
// deep cp.async pipeline (wait_group 1, one sync/iter), fused B ldsm4.
// ============================================================
template<bool GROUPED, bool RELU, bool RES>
__global__ __launch_bounds__(512, 1)
void conv_mma_kernel(const __nv_bfloat16* __restrict__ Y,
                     const __nv_bfloat16* __restrict__ Wc,
                     const float* __restrict__ bias,
                     const float* __restrict__ res,
                     float* __restrict__ out)
{
    extern __shared__ __align__(16) char smem[];
    const uint32_t sb = (uint32_t)__cvta_generic_to_shared(smem);
    const int tid  = threadIdx.x;
    const int lane = tid & 31;
    const int w    = tid >> 5;
    const int wco  = w >> 3;            // 0..1: 32-co stripe within the 64-co half
    const int wpx  = w & 7;             // 0..7: pixel row (32 px)
    const int img  = blockIdx.x >> 3;
    const int co2  = (blockIdx.x >> 2) & 1;   // which 64-co half
    const int r0   = (blockIdx.x & 3) * 8;

    const int arow  = (lane & 7) + ((lane >> 3) & 1) * 8;
    const int akoff = (lane >> 4) * 16;
    // fused B ldsm4: lane -> (tile in pair, k-half, row)
    const int bjj   = lane >> 4;
    const int bkoff = ((lane >> 3) & 1) * 16;
    const int brow  = lane & 7;

    const char* Yb = (const char*)Y;
    const char* Wb = (const char*)Wc;

    auto stage_B = [&](int ch) {
        char* dst = smem + (ch & 1) * BBUF;
        const size_t ybase = (size_t)img * 1156 * 512 + (size_t)ch * 128;
        for (int i = tid; i < 2720; i += 512) {
            int row = i >> 3, c16 = i & 7;
            int hr = row / 34, hc = row - hr * 34;
            cp16(dst + row * 144 + c16 * 16,
                 Yb + ybase + ((size_t)(r0 + hr) * 34 + hc) * 512 + c16 * 16);
        }
    };
    auto stage_A = [&](int it) {
        int ch = it / 9, sh = it - ch * 9;
        char* dst = smem + WOFF + (it % 3) * WBUF;
        const char* src = Wb + (size_t)(sh * 4 + ch) * (WPERSHCH * 2);
        #pragma unroll
        for (int k2 = 0; k2 < 2; ++k2) {
            int i = k2 * 512 + tid;
            if (i < 512) {
                int co = i >> 3, c16 = i & 7;
                cp16(dst + co * 144 + c16 * 16,
                     src + (co2 * 64 + co) * 128 + c16 * 16);
            } else if (i < 768) {
                int j = i - 512;
                int co = j >> 2, c16 = j & 3;
                cp16(dst + V1OFF + co * 80 + c16 * 16,
                     src + 16384 + (co2 * 64 + co) * 64 + c16 * 16);
            }
        }
    };

    float acc[2][4][4];
    #pragma unroll
    for (int m = 0; m < 2; ++m)
        #pragma unroll
        for (int j = 0; j < 4; ++j)
            #pragma unroll
            for (int q = 0; q < 4; ++q) acc[m][j][q] = 0.f;

    stage_B(0); stage_A(0); cp_commit();   // G0
    stage_A(1); cp_commit();               // G1

    for (int it = 0; it < 36; ++it) {
        cp_wait1();            // groups through G(it) complete; G(it+1) may pend
        __syncthreads();

        const int ch = it / 9, sh = it - ch * 9;
        if (!GROUPED || ch == co2 * 2 + wco) {
            const int dr = sh / 3, dc = sh - dr * 3;
            const uint32_t bbase = sb + (ch & 1) * BBUF;
            const uint32_t abase = sb + WOFF + (it % 3) * WBUF;
            uint32_t paddr[2];
            #pragma unroll
            for (int p = 0; p < 2; ++p) {
                int srow = (wpx + dr) * 34 + (2 * p + bjj) * 8 + dc + brow;
                paddr[p] = bbase + srow * 144 + bkoff;
            }
            const uint32_t aA0 = abase + (wco * 32 + arow) * 144 + akoff;
            const uint32_t aA1 = abase + V1OFF + (wco * 32 + arow) * 80 + akoff;

            #pragma unroll
            for (int ks = 0; ks < 4; ++ks) {
                uint32_t bfr[4][2];
                #pragma unroll
                for (int p = 0; p < 2; ++p) {
                    uint32_t t4[4];
                    ldsm4(t4, paddr[p] + ks * 32);
                    bfr[2*p][0] = t4[0]; bfr[2*p][1] = t4[1];
                    bfr[2*p+1][0] = t4[2]; bfr[2*p+1][1] = t4[3];
                }
                uint32_t a0[4], a1[4];
                ldsm4(a0, aA0 + ks * 32);
                ldsm4(a1, aA0 + 16 * 144 + ks * 32);
                #pragma unroll
                for (int j = 0; j < 4; ++j) {
                    mma16816(acc[0][j], a0, bfr[j]);
                    mma16816(acc[1][j], a1, bfr[j]);
                }
                if (ks < 2) {
                    uint32_t c0[4], c1[4];
                    ldsm4(c0, aA1 + ks * 32);
                    ldsm4(c1, aA1 + 16 * 80 + ks * 32);
                    #pragma unroll
                    for (int j = 0; j < 4; ++j) {
                        mma16816(acc[0][j], c0, bfr[j]);
                        mma16816(acc[1][j], c1, bfr[j]);
                    }
                }
            }
        }

        if (it + 2 < 36) {
            stage_A(it + 2);
            if ((it + 2) % 9 == 0) stage_B((it + 2) / 9);
        }
        cp_commit();           // exactly one group per iteration (maybe empty)
    }

    // ---- epilogue: planar coalesced fp32 stores ----
    #pragma unroll
    for (int m = 0; m < 2; ++m) {
        const int cobase = co2 * 64 + wco * 32 + m * 16 + (lane >> 2);
        const float b0 = bias[cobase], b1 = bias[cobase + 8];
        #pragma unroll
        for (int j = 0; j < 4; ++j) {
            const int gp = (r0 + wpx) * 32 + j * 8 + (lane & 3) * 2;
            float v0 = acc[m][j][0] + b0, v1 = acc[m][j][1] + b0;
            float v2 = acc[m][j][2] + b1, v3 = acc[m][j][3] + b1;
            if (RELU) {
                v0 = fmaxf(v0, 0.f); v1 = fmaxf(v1, 0.f);
                v2 = fmaxf(v2, 0.f); v3 = fmaxf(v3, 0.f);
            }
            size_t o = ((size_t)img * CC + cobase) * NPIX + gp;
            if (RES) { v0 += res[o]; v1 += res[o + 1]; }
            out[o] = v0; out[o + 1] = v1;
            size_t o2 = ((size_t)img * CC + cobase + 8) * NPIX + gp;
            if (RES) { v2 += res[o2]; v3 += res[o2 + 1]; }
            out[o2] = v2; out[o2 + 1] = v3;
        }
    }
}

// ============================================================
// attention-key logits: single-sync, all 32 planes in dynamic smem
// ============================================================
__global__ __launch_bounds__(256)
void ak_kernel(const float* __restrict__ v, const float* __restrict__ attw,
               float* __restrict__ ak)
{
    extern __shared__ float aksm[];          // [32][1156] + [288]
    float* sw = aksm + 32 * 1156;
    const int head = blockIdx.x & 3, bt = blockIdx.x >> 2;
    const int b = bt / TT, t = bt % TT;
    const int tid = threadIdx.x, pr = tid >> 3, pc = (tid & 7) * 4;

    for (int ci = 0; ci < 32; ++ci) {
        const float div  = __expf(-(float)(ci >> 1) * (logf(10000.0f) / 16.0f));
        const float ang  = (float)t * div;
        const float posv = (ci & 1) ? cosf(ang) : sinf(ang);
        const float* pl = v + ((size_t)bt * CC + head * DHH + ci) * NPIX;
        float* sp = aksm + ci * 1156;
        for (int idx = tid; idx < 1156; idx += 256) {
            int r = idx / 34 - 1, c = idx % 34 - 1;
            sp[idx] = (r >= 0 && r < 32 && c >= 0 && c < 32) ? (pl[r*32 + c] + posv) : 0.f;
        }
    }
    for (int i = tid; i < 288; i += 256)
        sw[i] = attw[((head * 64) + 32 + i / 9) * 9 + i % 9];
    __syncthreads();

    float acc[4] = {0.f, 0.f, 0.f, 0.f};
    for (int ci = 0; ci < 32; ++ci) {
        const float* sp = aksm + ci * 1156;
        float nb[3][6];
        #pragma unroll
        for (int r = 0; r < 3; ++r)
            #pragma unroll
            for (int c = 0; c < 6; ++c) nb[r][c] = sp[(pr + r) * 34 + pc + c];
        const float* wp = sw + ci * 9;
        #pragma unroll
        for (int p = 0; p < 4; ++p) {
            float s = acc[p];
            s += wp[0]*nb[0][p] + wp[1]*nb[0][p+1] + wp[2]*nb[0][p+2];
            s += wp[3]*nb[1][p] + wp[4]*nb[1][p+1] + wp[5]*nb[1][p+2];
            s += wp[6]*nb[2][p] + wp[7]*nb[2][p+1] + wp[8]*nb[2][p+2];
            acc[p] = s;
        }
    }
    #pragma unroll
    for (int p = 0; p < 4; ++p)
        ak[(((size_t)(b * NHEAD + head) * TT) + t) * NPIX + pr * 32 + pc + p] = acc[p];
}

// ============================================================
__global__ __launch_bounds__(256)
void softmax_ws_kernel(const float* __restrict__ ak, const float* __restrict__ v,
                       float* __restrict__ ws)
{
    const int chunk = blockIdx.x & 3;
    const int gid   = (blockIdx.x >> 2) * 256 + threadIdx.x;
    const int pix = gid & 1023, head = (gid >> 10) & 3, b = gid >> 12;
    float lg[TT], m = -1e30f;
    #pragma unroll
    for (int t = 0; t < TT; ++t) {
        lg[t] = ak[(((size_t)(b * NHEAD + head) * TT) + t) * NPIX + pix];
        m = fmaxf(m, lg[t]);
    }
    float s = 0.f;
    #pragma unroll
    for (int t = 0; t < TT; ++t) { lg[t] = expf(lg[t] - m); s += lg[t]; }
    const float inv = 1.f / s;
    const int c0 = chunk * 8;
    #pragma unroll
    for (int cc = 0; cc < 8; ++cc) {
        int c = c0 + cc;
        float a = 0.f;
        #pragma unroll
        for (int t = 0; t < TT; ++t)
            a += lg[t] * v[((size_t)(b * TT + t) * CC + head * DHH + c) * NPIX + pix];
        ws[((size_t)b * CC + head * DHH + c) * NPIX + pix] = a * inv;
    }
}

// ============================================================
__global__ __launch_bounds__(256)
void groupnorm_kernel(const float* __restrict__ in, const float* __restrict__ gnw,
                      const float* __restrict__ gnb, float* __restrict__ out)
{
    __shared__ float rs[256], rs2[256];
    const int n = blockIdx.x >> 2, g = blockIdx.x & 3, tid = threadIdx.x;
    const float* p = in + (size_t)n * IMG + (size_t)g * 32 * NPIX;
    float s = 0.f, s2 = 0.f;
    for (int i = tid; i < 32 * NPIX; i += 256) { float x = p[i]; s += x; s2 += x * x; }
    rs[tid] = s; rs2[tid] = s2;
    __syncthreads();
    for (int off = 128; off > 0; off >>= 1) {
        if (tid < off) { rs[tid] += rs[tid + off]; rs2[tid] += rs2[tid + off]; }
        __syncthreads();
    }
    const float mean = rs[0] * (1.f / 32768.f);
    const float var  = rs2[0] * (1.f / 32768.f) - mean * mean;
    const float rstd = rsqrtf(var + 1e-5f);
    float* o = out + (size_t)n * IMG + (size_t)g * 32 * NPIX;
    for (int i = tid; i < 32 * NPIX; i += 256) {
        int c = g * 32 + (i >> 10);
        o[i] = (p[i] - mean) * rstd * gnw[c] + gnb[c];
    }
}

// ============================================================
extern "C" void kernel_launch(void* const* d_in, const int* in_sizes, int n_in,
                              void* d_out, int out_size)
{
    const float* x0   = (const float*)d_in[0];
    // q_w, q_b, att_b cancel exactly in the softmax
    const float* kvw  = (const float*)d_in[3];
    const float* kvb  = (const float*)d_in[4];
    const float* attw = (const float*)d_in[5];
    const float* ff1w = (const float*)d_in[7];
    const float* ff1b = (const float*)d_in[8];
    const float* ff2w = (const float*)d_in[9];
    const float* ff2b = (const float*)d_in[10];
    const float* gnw  = (const float*)d_in[11];
    const float* gnb  = (const float*)d_in[12];

    float *cur, *v, *ak, *ws, *att, *ff1, *ff2;
    __nv_bfloat16 *Y, *Wp;
    cudaGetSymbolAddress((void**)&cur, g_cur);
    cudaGetSymbolAddress((void**)&v,   g_v);
    cudaGetSymbolAddress((void**)&ak,  g_ak);
    cudaGetSymbolAddress((void**)&ws,  g_ws);
    cudaGetSymbolAddress((void**)&att, g_att);
    cudaGetSymbolAddress((void**)&ff1, g_ff1);
    cudaGetSymbolAddress((void**)&ff2, g_ff2);
    cudaGetSymbolAddress((void**)&Y,   g_Y);
    cudaGetSymbolAddress((void**)&Wp,  g_Wp);

    cudaFuncSetAttribute(conv_mma_kernel<true, false,false>, cudaFuncAttributeMaxDynamicSharedMemorySize, CSMEM);
    cudaFuncSetAttribute(conv_mma_kernel<false,true, false>, cudaFuncAttributeMaxDynamicSharedMemorySize, CSMEM);
    cudaFuncSetAttribute(conv_mma_kernel<false,false,true >, cudaFuncAttributeMaxDynamicSharedMemorySize, CSMEM);
    cudaFuncSetAttribute(ak_kernel, cudaFuncAttributeMaxDynamicSharedMemorySize, AKSMEM);

    wprep_kernel<<<(WPTOT + 255) / 256, 256>>>(kvw, ff1w, ff2w, Wp);
    yzero_kernel<<<(YTOT / 2 + 255) / 256, 256>>>((unsigned*)Y);

    const float* lin = x0;
    for (int l = 0; l < 5; ++l) {
        prep_kernel<false><<<NT * 32, 256>>>(lin, nullptr, nullptr, Y);
        conv_mma_kernel<true,false,false><<<192, 512, CSMEM>>>(
            Y, Wp + (size_t)(l * 3 + 0) * WPERCONV, kvb + l * 128, nullptr, v);
        ak_kernel<<<NT * NHEAD, 256, AKSMEM>>>(v, attw + (size_t)l * 4 * 64 * 9, ak);
        softmax_ws_kernel<<<128, 256>>>(ak, v, ws);
        prep_kernel<true><<<NT * 32, 256>>>(lin, ws, att, Y);
        conv_mma_kernel<false,true,false><<<192, 512, CSMEM>>>(
            Y, Wp + (size_t)(l * 3 + 1) * WPERCONV, ff1b + l * 128, nullptr, ff1);
        prep_kernel<false><<<NT * 32, 256>>>(ff1, nullptr, nullptr, Y);
        conv_mma_kernel<false,false,true><<<192, 512, CSMEM>>>(
            Y, Wp + (size_t)(l * 3 + 2) * WPERCONV, ff2b + l * 128, att, ff2);
        float* lout = (l == 4) ? (float*)d_out : cur;
        groupnorm_kernel<<<NT * 4, 256>>>(ff2, gnw + l * 128, gnb + l * 128, lout);
        lin = cur;
    }
}

// round 14
// speedup vs baseline: 1.1790x; 1.1790x over previous
#include <cuda_runtime.h>
#include <cuda_bf16.h>
#include <math.h>
#include <stdint.h>

#define BB 2
#define TT 12
#define CC 128
#define NHEAD 4
#define DHH 32
#define NPIX 1024
#define NT (BB*TT)
#define IMG (CC*NPIX)
#define TOT (NT*IMG)

#define YTOT (NT*1156*256)
#define WPERSHCH 12288
#define WPERCONV (36*WPERSHCH)
#define WPTOT (15*WPERCONV)

// ---- scratch ----
__device__ float g_cur[TOT];
__device__ float g_v[TOT];
__device__ float g_ak[BB*NHEAD*TT*NPIX];
__device__ float g_ws[BB*CC*NPIX];
__device__ float g_att[TOT];
__device__ float g_ff1[TOT];
__device__ float g_ff2[TOT];
__device__ __nv_bfloat16 g_Y[YTOT];
__device__ __nv_bfloat16 g_Wp[WPTOT];

// ---- smem layout for ff conv kernel (dynamic) ----
#define BBUF 48960                 // 340 pixel-rows * 144B
#define V1OFF 18432                // var0: 128 rows * 144B
#define WBUF 28672                 // + var1: 128 rows * 80B
#define WOFF (2*BBUF)              // 97920
#define CSMEM (2*BBUF + 3*WBUF)    // 183936

// ---- kv kernel smem: full-channel B (swizzled, no pad) + 2 diag-A bufs ----
#define KVB_BYTES (340*512)        // 174080
#define KVA_OFF   KVB_BYTES
#define KVSMEM    (KVB_BYTES + 2*WBUF)   // 231424 (<= 232448 opt-in)

#define AKSMEM (32*1156*4 + 288*4) // 149120

// ---- PTX helpers ----
__device__ __forceinline__ void cp16(void* d, const void* s) {
    unsigned a = (unsigned)__cvta_generic_to_shared(d);
    asm volatile("cp.async.cg.shared.global [%0], [%1], 16;" :: "r"(a), "l"(s));
}
__device__ __forceinline__ void cp_commit() { asm volatile("cp.async.commit_group;" ::: "memory"); }
__device__ __forceinline__ void cp_wait1()  { asm volatile("cp.async.wait_group 1;" ::: "memory"); }

__device__ __forceinline__ void ldsm4(uint32_t* r, uint32_t a) {
    asm volatile("ldmatrix.sync.aligned.m8n8.x4.shared.b16 {%0,%1,%2,%3}, [%4];"
        : "=r"(r[0]), "=r"(r[1]), "=r"(r[2]), "=r"(r[3]) : "r"(a));
}
__device__ __forceinline__ void mma16816(float* d, const uint32_t* a, const uint32_t* b) {
    asm volatile("mma.sync.aligned.m16n8k16.row.col.f32.bf16.bf16.f32 "
        "{%0,%1,%2,%3}, {%4,%5,%6,%7}, {%8,%9}, {%0,%1,%2,%3};"
        : "+f"(d[0]), "+f"(d[1]), "+f"(d[2]), "+f"(d[3])
        : "r"(a[0]), "r"(a[1]), "r"(a[2]), "r"(a[3]), "r"(b[0]), "r"(b[1]));
}

// ============================================================
// weight prep: var0 (K64) = [w_hi|w_hi]; var1 (K32) = [w_lo]
// kv conv expanded block-diagonal into dense 128x128.
// ============================================================
__global__ __launch_bounds__(256)
void wprep_kernel(const float* __restrict__ kvw, const float* __restrict__ ff1w,
                  const float* __restrict__ ff2w, __nv_bfloat16* __restrict__ Wp)
{
    int idx = blockIdx.x * 256 + threadIdx.x;
    if (idx >= WPTOT) return;
    int conv = idx / WPERCONV;
    int o    = idx - conv * WPERCONV;
    int t    = o / WPERSHCH;
    int r    = o - t * WPERSHCH;
    int sh = t >> 2, ch = t & 3;
    int l = conv / 3, type = conv - l * 3;
    int kr = sh / 3, kc = sh - kr * 3;
    int var, co, k;
    if (r < 8192) { var = 0; co = r >> 6; k = r & 63; }
    else          { var = 1; int r2 = r - 8192; co = r2 >> 5; k = r2 & 31; }
    int cil = k & 31;
    float w;
    if (type == 0) {
        w = ((co >> 5) == ch)
          ? kvw[((((size_t)l * 4 + ch) * 32 + (co & 31)) * 32 + cil) * 9 + kr * 3 + kc]
          : 0.f;
    } else {
        const float* W = (type == 1) ? ff1w : ff2w;
        w = W[(((size_t)l * 128 + co) * 128 + ch * 32 + cil) * 9 + kr * 3 + kc];
    }
    __nv_bfloat16 hi = __float2bfloat16(w);
    Wp[idx] = (var == 0) ? hi : __float2bfloat16(w - __bfloat162float(hi));
}

__global__ __launch_bounds__(256)
void yzero_kernel(unsigned* __restrict__ Y32)
{
    size_t i = (size_t)blockIdx.x * 256 + threadIdx.x;
    if (i < YTOT / 2) Y32[i] = 0u;
}

// ============================================================
// planar fp32 -> Y split (coalesced); WS: input = x + ws, also writes att
// ============================================================
template<bool WS>
__global__ __launch_bounds__(256)
void prep_kernel(const float* __restrict__ x, const float* __restrict__ ws,
                 float* __restrict__ att, __nv_bfloat16* __restrict__ Y)
{
    __shared__ float sm[128 * 33];
    const int img = blockIdx.x >> 5;
    const int row = blockIdx.x & 31;
    const int tid = threadIdx.x;
    const int c   = tid & 31;
    const int ci0 = tid >> 5;
    const int b   = img / TT;
    const float* xp = x + (size_t)img * IMG + row * 32;
    #pragma unroll
    for (int k = 0; k < 16; ++k) {
        int ci = ci0 * 16 + k;
        float val = xp[(size_t)ci * NPIX + c];
        if (WS) {
            val += ws[((size_t)b * CC + ci) * NPIX + row * 32 + c];
            att[(size_t)img * IMG + (size_t)ci * NPIX + row * 32 + c] = val;
        }
        sm[ci * 33 + c] = val;
    }
    __syncthreads();

    unsigned* out32 = reinterpret_cast<unsigned*>(Y + ((size_t)img * 1156 + (row + 1) * 34 + 1) * 256);
    const int q  = tid & 127;
    const int ph = tid >> 7;
    #pragma unroll
    for (int p = 0; p < 16; ++p) {
        int c2 = p * 2 + ph;
        unsigned pk = 0;
        #pragma unroll
        for (int half = 0; half < 2; ++half) {
            int e  = q * 2 + half;
            int ch = e >> 6, r6 = e & 63;
            float xv = sm[(ch * 32 + (r6 & 31)) * 33 + c2];
            __nv_bfloat16 hi = __float2bfloat16(xv);
            __nv_bfloat16 v  = (r6 >= 32) ? __float2bfloat16(xv - __bfloat162float(hi)) : hi;
            pk |= ((unsigned)__bfloat16_as_ushort(v)) << (16 * half);
        }
        out32[(size_t)c2 * 128 + q] = pk;
    }
}

// ============================================================
// dense ff conv via mma.sync: D[128co x 256pix] per CTA, grid 96,
// deep cp.async pipeline (wait_group 1, one sync/iter), fused B ldsm4.
// ============================================================
template<bool RELU, bool RES>
__global__ __launch_bounds__(512, 1)
void conv_mma_kernel(const __nv_bfloat16* __restrict__ Y,
                     const __nv_bfloat16* __restrict__ Wc,
                     const float* __restrict__ bias,
                     const float* __restrict__ res,
                     float* __restrict__ out)
{
    extern __shared__ __align__(16) char smem[];
    const uint32_t sb = (uint32_t)__cvta_generic_to_shared(smem);
    const int tid  = threadIdx.x;
    const int lane = tid & 31;
    const int w    = tid >> 5;
    const int wco  = w >> 2;
    const int wpx  = w & 3;
    const int img  = blockIdx.x >> 2;
    const int r0   = (blockIdx.x & 3) * 8;

    const int arow  = (lane & 7) + ((lane >> 3) & 1) * 8;
    const int akoff = (lane >> 4) * 16;
    const int bjj   = lane >> 4;
    const int bkoff = ((lane >> 3) & 1) * 16;
    const int brow  = lane & 7;

    const char* Yb = (const char*)Y;
    const char* Wb = (const char*)Wc;

    auto stage_B = [&](int ch) {
        char* dst = smem + (ch & 1) * BBUF;
        const size_t ybase = (size_t)img * 1156 * 512 + (size_t)ch * 128;
        for (int i = tid; i < 2720; i += 512) {
            int row = i >> 3, c16 = i & 7;
            int hr = row / 34, hc = row - hr * 34;
            cp16(dst + row * 144 + c16 * 16,
                 Yb + ybase + ((size_t)(r0 + hr) * 34 + hc) * 512 + c16 * 16);
        }
    };
    auto stage_A = [&](int it) {
        int ch = it / 9, sh = it - ch * 9;
        char* dst = smem + WOFF + (it % 3) * WBUF;
        const char* src = Wb + (size_t)(sh * 4 + ch) * (WPERSHCH * 2);
        #pragma unroll
        for (int k2 = 0; k2 < 3; ++k2) {
            int i = k2 * 512 + tid;
            if (i < 1024) {
                int co = i >> 3, c16 = i & 7;
                cp16(dst + co * 144 + c16 * 16, src + co * 128 + c16 * 16);
            } else {
                int j = i - 1024;
                int co = j >> 2, c16 = j & 3;
                cp16(dst + V1OFF + co * 80 + c16 * 16, src + 16384 + co * 64 + c16 * 16);
            }
        }
    };

    float acc[2][8][4];
    #pragma unroll
    for (int m = 0; m < 2; ++m)
        #pragma unroll
        for (int j = 0; j < 8; ++j)
            #pragma unroll
            for (int q = 0; q < 4; ++q) acc[m][j][q] = 0.f;

    stage_B(0); stage_A(0); cp_commit();   // G0
    stage_A(1); cp_commit();               // G1

    for (int it = 0; it < 36; ++it) {
        cp_wait1();
        __syncthreads();

        const int ch = it / 9, sh = it - ch * 9;
        {
            const int dr = sh / 3, dc = sh - dr * 3;
            const uint32_t bbase = sb + (ch & 1) * BBUF;
            const uint32_t abase = sb + WOFF + (it % 3) * WBUF;
            uint32_t paddr[4];
            #pragma unroll
            for (int p = 0; p < 4; ++p) {
                int srow = (wpx * 2 + (p >> 1) + dr) * 34
                         + ((p & 1) * 2 + bjj) * 8 + dc + brow;
                paddr[p] = bbase + srow * 144 + bkoff;
            }
            const uint32_t aA0 = abase + (wco * 32 + arow) * 144 + akoff;
            const uint32_t aA1 = abase + V1OFF + (wco * 32 + arow) * 80 + akoff;

            #pragma unroll
            for (int ks = 0; ks < 4; ++ks) {
                uint32_t bfr[8][2];
                #pragma unroll
                for (int p = 0; p < 4; ++p) {
                    uint32_t t4[4];
                    ldsm4(t4, paddr[p] + ks * 32);
                    bfr[2*p][0] = t4[0]; bfr[2*p][1] = t4[1];
                    bfr[2*p+1][0] = t4[2]; bfr[2*p+1][1] = t4[3];
                }
                uint32_t a0[4], a1[4];
                ldsm4(a0, aA0 + ks * 32);
                ldsm4(a1, aA0 + 16 * 144 + ks * 32);
                #pragma unroll
                for (int j = 0; j < 8; ++j) {
                    mma16816(acc[0][j], a0, bfr[j]);
                    mma16816(acc[1][j], a1, bfr[j]);
                }
                if (ks < 2) {
                    uint32_t c0[4], c1[4];
                    ldsm4(c0, aA1 + ks * 32);
                    ldsm4(c1, aA1 + 16 * 80 + ks * 32);
                    #pragma unroll
                    for (int j = 0; j < 8; ++j) {
                        mma16816(acc[0][j], c0, bfr[j]);
                        mma16816(acc[1][j], c1, bfr[j]);
                    }
                }
            }
        }

        if (it + 2 < 36) {
            stage_A(it + 2);
            if ((it + 2) % 9 == 0) stage_B((it + 2) / 9);
        }
        cp_commit();
    }

    // ---- epilogue: planar coalesced fp32 stores ----
    #pragma unroll
    for (int m = 0; m < 2; ++m) {
        const int cobase = wco * 32 + m * 16 + (lane >> 2);
        const float b0 = bias[cobase], b1 = bias[cobase + 8];
        #pragma unroll
        for (int j = 0; j < 8; ++j) {
            const int gp = r0 * 32 + wpx * 64 + j * 8 + (lane & 3) * 2;
            float v0 = acc[m][j][0] + b0, v1 = acc[m][j][1] + b0;
            float v2 = acc[m][j][2] + b1, v3 = acc[m][j][3] + b1;
            if (RELU) {
                v0 = fmaxf(v0, 0.f); v1 = fmaxf(v1, 0.f);
                v2 = fmaxf(v2, 0.f); v3 = fmaxf(v3, 0.f);
            }
            size_t o = ((size_t)img * CC + cobase) * NPIX + gp;
            if (RES) { v0 += res[o]; v1 += res[o + 1]; }
            out[o] = v0; out[o + 1] = v1;
            size_t o2 = ((size_t)img * CC + cobase + 8) * NPIX + gp;
            if (RES) { v2 += res[o2]; v3 += res[o2 + 1]; }
            out[o2] = v2; out[o2 + 1] = v3;
        }
    }
}

// ============================================================
// kv conv (block-diagonal): 9 iterations over shifts only.
// B = full-channel per pixel (512B), staged ONCE, XOR-16B row swizzle.
// Warp stripe wco computes its own chunk every iteration.
// ============================================================
__global__ __launch_bounds__(512, 1)
void conv_kv_kernel(const __nv_bfloat16* __restrict__ Y,
                    const __nv_bfloat16* __restrict__ Wc,
                    const float* __restrict__ bias,
                    float* __restrict__ out)
{
    extern __shared__ __align__(16) char smem[];
    const uint32_t sb = (uint32_t)__cvta_generic_to_shared(smem);
    const int tid  = threadIdx.x;
    const int lane = tid & 31;
    const int w    = tid >> 5;
    const int wco  = w >> 2;            // 0..3 = co stripe AND its diagonal chunk
    const int wpx  = w & 3;
    const int img  = blockIdx.x >> 2;
    const int r0   = (blockIdx.x & 3) * 8;

    const int arow  = (lane & 7) + ((lane >> 3) & 1) * 8;
    const int akoff = (lane >> 4) * 16;
    const int bjj   = lane >> 4;
    const int khalf = (lane >> 3) & 1;
    const int brow  = lane & 7;

    const char* Yb = (const char*)Y;
    const char* Wb = (const char*)Wc;

    // ---- stage full-channel B once (340 pixel rows x 512B, swizzled) ----
    {
        const size_t ybase = (size_t)img * 1156 * 512;
        for (int i = tid; i < 340 * 32; i += 512) {
            int row = i >> 5, slot = i & 31;
            int hr = row / 34, hc = row - hr * 34;
            cp16(smem + row * 512 + ((slot ^ (row & 7)) << 4),
                 Yb + ybase + ((size_t)(r0 + hr) * 34 + hc) * 512 + slot * 16);
        }
    }
    // ---- diagonal A stage for one shift: rows s=0..127, chunk = s>>5 ----
    auto stage_A = [&](int sh) {
        char* dst = smem + KVA_OFF + (sh & 1) * WBUF;
        #pragma unroll
        for (int k2 = 0; k2 < 3; ++k2) {
            int i = k2 * 512 + tid;
            if (i < 1024) {
                int s = i >> 3, c16 = i & 7;
                const char* src = Wb + (size_t)(sh * 4 + (s >> 5)) * (WPERSHCH * 2);
                cp16(dst + s * 144 + c16 * 16, src + s * 128 + c16 * 16);
            } else {
                int j = i - 1024;
                int s = j >> 2, c16 = j & 3;
                const char* src = Wb + (size_t)(sh * 4 + (s >> 5)) * (WPERSHCH * 2);
                cp16(dst + V1OFF + s * 80 + c16 * 16, src + 16384 + s * 64 + c16 * 16);
            }
        }
    };

    float acc[2][8][4];
    #pragma unroll
    for (int m = 0; m < 2; ++m)
        #pragma unroll
        for (int j = 0; j < 8; ++j)
            #pragma unroll
            for (int q = 0; q < 4; ++q) acc[m][j][q] = 0.f;

    stage_A(0); cp_commit();     // G0 = B + A0
    stage_A(1); cp_commit();     // G1 = A1

    for (int sh = 0; sh < 9; ++sh) {
        cp_wait1();
        __syncthreads();

        const int dr = sh / 3, dc = sh - dr * 3;
        uint32_t rb[4]; int s7[4];
        #pragma unroll
        for (int p = 0; p < 4; ++p) {
            int srow = (wpx * 2 + (p >> 1) + dr) * 34
                     + ((p & 1) * 2 + bjj) * 8 + dc + brow;
            rb[p] = sb + srow * 512;
            s7[p] = srow & 7;
        }
        const uint32_t abase = sb + KVA_OFF + (sh & 1) * WBUF;
        const uint32_t aA0 = abase + (wco * 32 + arow) * 144 + akoff;
        const uint32_t aA1 = abase + V1OFF + (wco * 32 + arow) * 80 + akoff;

        #pragma unroll
        for (int ks = 0; ks < 4; ++ks) {
            const int k16 = wco * 8 + ks * 2 + khalf;
            uint32_t bfr[8][2];
            #pragma unroll
            for (int p = 0; p < 4; ++p) {
                uint32_t t4[4];
                ldsm4(t4, rb[p] + ((k16 ^ s7[p]) << 4));
                bfr[2*p][0] = t4[0]; bfr[2*p][1] = t4[1];
                bfr[2*p+1][0] = t4[2]; bfr[2*p+1][1] = t4[3];
            }
            uint32_t a0[4], a1[4];
            ldsm4(a0, aA0 + ks * 32);
            ldsm4(a1, aA0 + 16 * 144 + ks * 32);
            #pragma unroll
            for (int j = 0; j < 8; ++j) {
                mma16816(acc[0][j], a0, bfr[j]);
                mma16816(acc[1][j], a1, bfr[j]);
            }
            if (ks < 2) {
                uint32_t c0[4], c1[4];
                ldsm4(c0, aA1 + ks * 32);
                ldsm4(c1, aA1 + 16 * 80 + ks * 32);
                #pragma unroll
                for (int j = 0; j < 8; ++j) {
                    mma16816(acc[0][j], c0, bfr[j]);
                    mma16816(acc[1][j], c1, bfr[j]);
                }
            }
        }

        if (sh + 2 < 9) stage_A(sh + 2);
        cp_commit();
    }

    // ---- epilogue ----
    #pragma unroll
    for (int m = 0; m < 2; ++m) {
        const int cobase = wco * 32 + m * 16 + (lane >> 2);
        const float b0 = bias[cobase], b1 = bias[cobase + 8];
        #pragma unroll
        for (int j = 0; j < 8; ++j) {
            const int gp = r0 * 32 + wpx * 64 + j * 8 + (lane & 3) * 2;
            size_t o = ((size_t)img * CC + cobase) * NPIX + gp;
            out[o]     = acc[m][j][0] + b0;
            out[o + 1] = acc[m][j][1] + b0;
            size_t o2 = ((size_t)img * CC + cobase + 8) * NPIX + gp;
            out[o2]     = acc[m][j][2] + b1;
            out[o2 + 1] = acc[m][j][3] + b1;
        }
    }
}

// ============================================================
// attention-key logits: single-sync, all 32 planes in dynamic smem
// ============================================================
__global__ __launch_bounds__(256)
void ak_kernel(const float* __restrict__ v, const float* __restrict__ attw,
               float* __restrict__ ak)
{
    extern __shared__ float aksm[];          // [32][1156] + [288]
    float* sw = aksm + 32 * 1156;
    const int head = blockIdx.x & 3, bt = blockIdx.x >> 2;
    const int b = bt / TT, t = bt % TT;
    const int tid = threadIdx.x, pr = tid >> 3, pc = (tid & 7) * 4;

    for (int ci = 0; ci < 32; ++ci) {
        const float div  = __expf(-(float)(ci >> 1) * (logf(10000.0f) / 16.0f));
        const float ang  = (float)t * div;
        const float posv = (ci & 1) ? cosf(ang) : sinf(ang);
        const float* pl = v + ((size_t)bt * CC + head * DHH + ci) * NPIX;
        float* sp = aksm + ci * 1156;
        for (int idx = tid; idx < 1156; idx += 256) {
            int r = idx / 34 - 1, c = idx % 34 - 1;
            sp[idx] = (r >= 0 && r < 32 && c >= 0 && c < 32) ? (pl[r*32 + c] + posv) : 0.f;
        }
    }
    for (int i = tid; i < 288; i += 256)
        sw[i] = attw[((head * 64) + 32 + i / 9) * 9 + i % 9];
    __syncthreads();

    float acc[4] = {0.f, 0.f, 0.f, 0.f};
    for (int ci = 0; ci < 32; ++ci) {
        const float* sp = aksm + ci * 1156;
        float nb[3][6];
        #pragma unroll
        for (int r = 0; r < 3; ++r)
            #pragma unroll
            for (int c = 0; c < 6; ++c) nb[r][c] = sp[(pr + r) * 34 + pc + c];
        const float* wp = sw + ci * 9;
        #pragma unroll
        for (int p = 0; p < 4; ++p) {
            float s = acc[p];
            s += wp[0]*nb[0][p] + wp[1]*nb[0][p+1] + wp[2]*nb[0][p+2];
            s += wp[3]*nb[1][p] + wp[4]*nb[1][p+1] + wp[5]*nb[1][p+2];
            s += wp[6]*nb[2][p] + wp[7]*nb[2][p+1] + wp[8]*nb[2][p+2];
            acc[p] = s;
        }
    }
    #pragma unroll
    for (int p = 0; p < 4; ++p)
        ak[(((size_t)(b * NHEAD + head) * TT) + t) * NPIX + pr * 32 + pc + p] = acc[p];
}

// ============================================================
__global__ __launch_bounds__(256)
void softmax_ws_kernel(const float* __restrict__ ak, const float* __restrict__ v,
                       float* __restrict__ ws)
{
    const int chunk = blockIdx.x & 3;
    const int gid   = (blockIdx.x >> 2) * 256 + threadIdx.x;
    const int pix = gid & 1023, head = (gid >> 10) & 3, b = gid >> 12;
    float lg[TT], m = -1e30f;
    #pragma unroll
    for (int t = 0; t < TT; ++t) {
        lg[t] = ak[(((size_t)(b * NHEAD + head) * TT) + t) * NPIX + pix];
        m = fmaxf(m, lg[t]);
    }
    float s = 0.f;
    #pragma unroll
    for (int t = 0; t < TT; ++t) { lg[t] = expf(lg[t] - m); s += lg[t]; }
    const float inv = 1.f / s;
    const int c0 = chunk * 8;
    #pragma unroll
    for (int cc = 0; cc < 8; ++cc) {
        int c = c0 + cc;
        float a = 0.f;
        #pragma unroll
        for (int t = 0; t < TT; ++t)
            a += lg[t] * v[((size_t)(b * TT + t) * CC + head * DHH + c) * NPIX + pix];
        ws[((size_t)b * CC + head * DHH + c) * NPIX + pix] = a * inv;
    }
}

// ============================================================
__global__ __launch_bounds__(256)
void groupnorm_kernel(const float* __restrict__ in, const float* __restrict__ gnw,
                      const float* __restrict__ gnb, float* __restrict__ out)
{
    __shared__ float rs[256], rs2[256];
    const int n = blockIdx.x >> 2, g = blockIdx.x & 3, tid = threadIdx.x;
    const float* p = in + (size_t)n * IMG + (size_t)g * 32 * NPIX;
    float s = 0.f, s2 = 0.f;
    for (int i = tid; i < 32 * NPIX; i += 256) { float x = p[i]; s += x; s2 += x * x; }
    rs[tid] = s; rs2[tid] = s2;
    __syncthreads();
    for (int off = 128; off > 0; off >>= 1) {
        if (tid < off) { rs[tid] += rs[tid + off]; rs2[tid] += rs2[tid + off]; }
        __syncthreads();
    }
    const float mean = rs[0] * (1.f / 32768.f);
    const float var  = rs2[0] * (1.f / 32768.f) - mean * mean;
    const float rstd = rsqrtf(var + 1e-5f);
    float* o = out + (size_t)n * IMG + (size_t)g * 32 * NPIX;
    for (int i = tid; i < 32 * NPIX; i += 256) {
        int c = g * 32 + (i >> 10);
        o[i] = (p[i] - mean) * rstd * gnw[c] + gnb[c];
    }
}

// ============================================================
extern "C" void kernel_launch(void* const* d_in, const int* in_sizes, int n_in,
                              void* d_out, int out_size)
{
    const float* x0   = (const float*)d_in[0];
    // q_w, q_b, att_b cancel exactly in the softmax
    const float* kvw  = (const float*)d_in[3];
    const float* kvb  = (const float*)d_in[4];
    const float* attw = (const float*)d_in[5];
    const float* ff1w = (const float*)d_in[7];
    const float* ff1b = (const float*)d_in[8];
    const float* ff2w = (const float*)d_in[9];
    const float* ff2b = (const float*)d_in[10];
    const float* gnw  = (const float*)d_in[11];
    const float* gnb  = (const float*)d_in[12];

    float *cur, *v, *ak, *ws, *att, *ff1, *ff2;
    __nv_bfloat16 *Y, *Wp;
    cudaGetSymbolAddress((void**)&cur, g_cur);
    cudaGetSymbolAddress((void**)&v,   g_v);
    cudaGetSymbolAddress((void**)&ak,  g_ak);
    cudaGetSymbolAddress((void**)&ws,  g_ws);
    cudaGetSymbolAddress((void**)&att, g_att);
    cudaGetSymbolAddress((void**)&ff1, g_ff1);
    cudaGetSymbolAddress((void**)&ff2, g_ff2);
    cudaGetSymbolAddress((void**)&Y,   g_Y);
    cudaGetSymbolAddress((void**)&Wp,  g_Wp);

    cudaFuncSetAttribute(conv_mma_kernel<true, false>, cudaFuncAttributeMaxDynamicSharedMemorySize, CSMEM);
    cudaFuncSetAttribute(conv_mma_kernel<false,true >, cudaFuncAttributeMaxDynamicSharedMemorySize, CSMEM);
    cudaFuncSetAttribute(conv_kv_kernel, cudaFuncAttributeMaxDynamicSharedMemorySize, KVSMEM);
    cudaFuncSetAttribute(ak_kernel, cudaFuncAttributeMaxDynamicSharedMemorySize, AKSMEM);

    wprep_kernel<<<(WPTOT + 255) / 256, 256>>>(kvw, ff1w, ff2w, Wp);
    yzero_kernel<<<(YTOT / 2 + 255) / 256, 256>>>((unsigned*)Y);

    const float* lin = x0;
    for (int l = 0; l < 5; ++l) {
        prep_kernel<false><<<NT * 32, 256>>>(lin, nullptr, nullptr, Y);
        conv_kv_kernel<<<96, 512, KVSMEM>>>(
            Y, Wp + (size_t)(l * 3 + 0) * WPERCONV, kvb + l * 128, v);
        ak_kernel<<<NT * NHEAD, 256, AKSMEM>>>(v, attw + (size_t)l * 4 * 64 * 9, ak);
        softmax_ws_kernel<<<128, 256>>>(ak, v, ws);
        prep_kernel<true><<<NT * 32, 256>>>(lin, ws, att, Y);
        conv_mma_kernel<true,false><<<96, 512, CSMEM>>>(
            Y, Wp + (size_t)(l * 3 + 1) * WPERCONV, ff1b + l * 128, nullptr, ff1);
        prep_kernel<false><<<NT * 32, 256>>>(ff1, nullptr, nullptr, Y);
        conv_mma_kernel<false,true><<<96, 512, CSMEM>>>(
            Y, Wp + (size_t)(l * 3 + 2) * WPERCONV, ff2b + l * 128, att, ff2);
        float* lout = (l == 4) ? (float*)d_out : cur;
        groupnorm_kernel<<<NT * 4, 256>>>(ff2, gnw + l * 128, gnb + l * 128, lout);
        lin = cur;
    }
}

// round 15
// speedup vs baseline: 1.1863x; 1.0062x over previous
#include <cuda_runtime.h>
#include <cuda_bf16.h>
#include <math.h>
#include <stdint.h>

#define BB 2
#define TT 12
#define CC 128
#define NHEAD 4
#define DHH 32
#define NPIX 1024
#define NT (BB*TT)
#define IMG (CC*NPIX)
#define TOT (NT*IMG)

#define YTOT (NT*1156*256)
#define WPERSHCH 12288
#define WPERCONV (36*WPERSHCH)
#define WPTOT (15*WPERCONV)

// ---- scratch ----
__device__ float g_cur[TOT];
__device__ float g_v[TOT];
__device__ float g_ak[BB*NHEAD*TT*NPIX];
__device__ float g_ws[BB*CC*NPIX];
__device__ float g_att[TOT];
__device__ float g_ff1[TOT];
__device__ float g_ff2[TOT];
__device__ __nv_bfloat16 g_Y[YTOT];
__device__ __nv_bfloat16 g_Wp[WPTOT];

// ---- smem layout for ff conv kernel (dynamic) ----
#define BBUF 48960                 // 340 pixel-rows * 144B
#define V1OFF 18432                // var0: 128 rows * 144B
#define WBUF 28672                 // + var1: 128 rows * 80B
#define WOFF (2*BBUF)              // 97920
#define CSMEM (2*BBUF + 3*WBUF)    // 183936

// ---- kv kernel smem: full-channel B (swizzled, no pad) + 2 diag-A bufs ----
#define KVB_BYTES (340*512)        // 174080
#define KVA_OFF   KVB_BYTES
#define KVSMEM    (KVB_BYTES + 2*WBUF)   // 231424 (<= 232448 opt-in)

#define AKSMEM (32*1156*4 + 288*4) // 149120

// ---- PTX helpers ----
__device__ __forceinline__ void cp16(void* d, const void* s) {
    unsigned a = (unsigned)__cvta_generic_to_shared(d);
    asm volatile("cp.async.cg.shared.global [%0], [%1], 16;" :: "r"(a), "l"(s));
}
__device__ __forceinline__ void cp_commit() { asm volatile("cp.async.commit_group;" ::: "memory"); }
__device__ __forceinline__ void cp_wait0()  { asm volatile("cp.async.wait_group 0;" ::: "memory"); }
__device__ __forceinline__ void cp_wait1()  { asm volatile("cp.async.wait_group 1;" ::: "memory"); }

__device__ __forceinline__ void ldsm4(uint32_t* r, uint32_t a) {
    asm volatile("ldmatrix.sync.aligned.m8n8.x4.shared.b16 {%0,%1,%2,%3}, [%4];"
        : "=r"(r[0]), "=r"(r[1]), "=r"(r[2]), "=r"(r[3]) : "r"(a));
}
__device__ __forceinline__ void mma16816(float* d, const uint32_t* a, const uint32_t* b) {
    asm volatile("mma.sync.aligned.m16n8k16.row.col.f32.bf16.bf16.f32 "
        "{%0,%1,%2,%3}, {%4,%5,%6,%7}, {%8,%9}, {%0,%1,%2,%3};"
        : "+f"(d[0]), "+f"(d[1]), "+f"(d[2]), "+f"(d[3])
        : "r"(a[0]), "r"(a[1]), "r"(a[2]), "r"(a[3]), "r"(b[0]), "r"(b[1]));
}

// ============================================================
// weight prep: var0 (K64) = [w_hi|w_hi]; var1 (K32) = [w_lo]
// kv conv expanded block-diagonal into dense 128x128.
// ============================================================
__global__ __launch_bounds__(256)
void wprep_kernel(const float* __restrict__ kvw, const float* __restrict__ ff1w,
                  const float* __restrict__ ff2w, __nv_bfloat16* __restrict__ Wp)
{
    int idx = blockIdx.x * 256 + threadIdx.x;
    if (idx >= WPTOT) return;
    int conv = idx / WPERCONV;
    int o    = idx - conv * WPERCONV;
    int t    = o / WPERSHCH;
    int r    = o - t * WPERSHCH;
    int sh = t >> 2, ch = t & 3;
    int l = conv / 3, type = conv - l * 3;
    int kr = sh / 3, kc = sh - kr * 3;
    int var, co, k;
    if (r < 8192) { var = 0; co = r >> 6; k = r & 63; }
    else          { var = 1; int r2 = r - 8192; co = r2 >> 5; k = r2 & 31; }
    int cil = k & 31;
    float w;
    if (type == 0) {
        w = ((co >> 5) == ch)
          ? kvw[((((size_t)l * 4 + ch) * 32 + (co & 31)) * 32 + cil) * 9 + kr * 3 + kc]
          : 0.f;
    } else {
        const float* W = (type == 1) ? ff1w : ff2w;
        w = W[(((size_t)l * 128 + co) * 128 + ch * 32 + cil) * 9 + kr * 3 + kc];
    }
    __nv_bfloat16 hi = __float2bfloat16(w);
    Wp[idx] = (var == 0) ? hi : __float2bfloat16(w - __bfloat162float(hi));
}

__global__ __launch_bounds__(256)
void yzero_kernel(unsigned* __restrict__ Y32)
{
    size_t i = (size_t)blockIdx.x * 256 + threadIdx.x;
    if (i < YTOT / 2) Y32[i] = 0u;
}

// ============================================================
// planar fp32 -> Y split (coalesced); WS: input = x + ws, also writes att
// ============================================================
template<bool WS>
__global__ __launch_bounds__(256)
void prep_kernel(const float* __restrict__ x, const float* __restrict__ ws,
                 float* __restrict__ att, __nv_bfloat16* __restrict__ Y)
{
    __shared__ float sm[128 * 33];
    const int img = blockIdx.x >> 5;
    const int row = blockIdx.x & 31;
    const int tid = threadIdx.x;
    const int c   = tid & 31;
    const int ci0 = tid >> 5;
    const int b   = img / TT;
    const float* xp = x + (size_t)img * IMG + row * 32;
    #pragma unroll
    for (int k = 0; k < 16; ++k) {
        int ci = ci0 * 16 + k;
        float val = xp[(size_t)ci * NPIX + c];
        if (WS) {
            val += ws[((size_t)b * CC + ci) * NPIX + row * 32 + c];
            att[(size_t)img * IMG + (size_t)ci * NPIX + row * 32 + c] = val;
        }
        sm[ci * 33 + c] = val;
    }
    __syncthreads();

    unsigned* out32 = reinterpret_cast<unsigned*>(Y + ((size_t)img * 1156 + (row + 1) * 34 + 1) * 256);
    const int q  = tid & 127;
    const int ph = tid >> 7;
    #pragma unroll
    for (int p = 0; p < 16; ++p) {
        int c2 = p * 2 + ph;
        unsigned pk = 0;
        #pragma unroll
        for (int half = 0; half < 2; ++half) {
            int e  = q * 2 + half;
            int ch = e >> 6, r6 = e & 63;
            float xv = sm[(ch * 32 + (r6 & 31)) * 33 + c2];
            __nv_bfloat16 hi = __float2bfloat16(xv);
            __nv_bfloat16 v  = (r6 >= 32) ? __float2bfloat16(xv - __bfloat162float(hi)) : hi;
            pk |= ((unsigned)__bfloat16_as_ushort(v)) << (16 * half);
        }
        out32[(size_t)c2 * 128 + q] = pk;
    }
}

// ============================================================
// dense ff conv via mma.sync: D[128co x 256pix] per CTA, grid 96,
// deep cp.async pipeline (wait_group 1, mod-3 A ring -> race-free),
// fused B ldsm4.
// ============================================================
template<bool RELU, bool RES>
__global__ __launch_bounds__(512, 1)
void conv_mma_kernel(const __nv_bfloat16* __restrict__ Y,
                     const __nv_bfloat16* __restrict__ Wc,
                     const float* __restrict__ bias,
                     const float* __restrict__ res,
                     float* __restrict__ out)
{
    extern __shared__ __align__(16) char smem[];
    const uint32_t sb = (uint32_t)__cvta_generic_to_shared(smem);
    const int tid  = threadIdx.x;
    const int lane = tid & 31;
    const int w    = tid >> 5;
    const int wco  = w >> 2;
    const int wpx  = w & 3;
    const int img  = blockIdx.x >> 2;
    const int r0   = (blockIdx.x & 3) * 8;

    const int arow  = (lane & 7) + ((lane >> 3) & 1) * 8;
    const int akoff = (lane >> 4) * 16;
    const int bjj   = lane >> 4;
    const int bkoff = ((lane >> 3) & 1) * 16;
    const int brow  = lane & 7;

    const char* Yb = (const char*)Y;
    const char* Wb = (const char*)Wc;

    auto stage_B = [&](int ch) {
        char* dst = smem + (ch & 1) * BBUF;
        const size_t ybase = (size_t)img * 1156 * 512 + (size_t)ch * 128;
        for (int i = tid; i < 2720; i += 512) {
            int row = i >> 3, c16 = i & 7;
            int hr = row / 34, hc = row - hr * 34;
            cp16(dst + row * 144 + c16 * 16,
                 Yb + ybase + ((size_t)(r0 + hr) * 34 + hc) * 512 + c16 * 16);
        }
    };
    auto stage_A = [&](int it) {
        int ch = it / 9, sh = it - ch * 9;
        char* dst = smem + WOFF + (it % 3) * WBUF;
        const char* src = Wb + (size_t)(sh * 4 + ch) * (WPERSHCH * 2);
        #pragma unroll
        for (int k2 = 0; k2 < 3; ++k2) {
            int i = k2 * 512 + tid;
            if (i < 1024) {
                int co = i >> 3, c16 = i & 7;
                cp16(dst + co * 144 + c16 * 16, src + co * 128 + c16 * 16);
            } else {
                int j = i - 1024;
                int co = j >> 2, c16 = j & 3;
                cp16(dst + V1OFF + co * 80 + c16 * 16, src + 16384 + co * 64 + c16 * 16);
            }
        }
    };

    float acc[2][8][4];
    #pragma unroll
    for (int m = 0; m < 2; ++m)
        #pragma unroll
        for (int j = 0; j < 8; ++j)
            #pragma unroll
            for (int q = 0; q < 4; ++q) acc[m][j][q] = 0.f;

    stage_B(0); stage_A(0); cp_commit();   // G0
    stage_A(1); cp_commit();               // G1

    for (int it = 0; it < 36; ++it) {
        cp_wait1();
        __syncthreads();

        const int ch = it / 9, sh = it - ch * 9;
        {
            const int dr = sh / 3, dc = sh - dr * 3;
            const uint32_t bbase = sb + (ch & 1) * BBUF;
            const uint32_t abase = sb + WOFF + (it % 3) * WBUF;
            uint32_t paddr[4];
            #pragma unroll
            for (int p = 0; p < 4; ++p) {
                int srow = (wpx * 2 + (p >> 1) + dr) * 34
                         + ((p & 1) * 2 + bjj) * 8 + dc + brow;
                paddr[p] = bbase + srow * 144 + bkoff;
            }
            const uint32_t aA0 = abase + (wco * 32 + arow) * 144 + akoff;
            const uint32_t aA1 = abase + V1OFF + (wco * 32 + arow) * 80 + akoff;

            #pragma unroll
            for (int ks = 0; ks < 4; ++ks) {
                uint32_t bfr[8][2];
                #pragma unroll
                for (int p = 0; p < 4; ++p) {
                    uint32_t t4[4];
                    ldsm4(t4, paddr[p] + ks * 32);
                    bfr[2*p][0] = t4[0]; bfr[2*p][1] = t4[1];
                    bfr[2*p+1][0] = t4[2]; bfr[2*p+1][1] = t4[3];
                }
                uint32_t a0[4], a1[4];
                ldsm4(a0, aA0 + ks * 32);
                ldsm4(a1, aA0 + 16 * 144 + ks * 32);
                #pragma unroll
                for (int j = 0; j < 8; ++j) {
                    mma16816(acc[0][j], a0, bfr[j]);
                    mma16816(acc[1][j], a1, bfr[j]);
                }
                if (ks < 2) {
                    uint32_t c0[4], c1[4];
                    ldsm4(c0, aA1 + ks * 32);
                    ldsm4(c1, aA1 + 16 * 80 + ks * 32);
                    #pragma unroll
                    for (int j = 0; j < 8; ++j) {
                        mma16816(acc[0][j], c0, bfr[j]);
                        mma16816(acc[1][j], c1, bfr[j]);
                    }
                }
            }
        }

        if (it + 2 < 36) {
            stage_A(it + 2);
            if ((it + 2) % 9 == 0) stage_B((it + 2) / 9);
        }
        cp_commit();
    }

    // ---- epilogue: planar coalesced fp32 stores ----
    #pragma unroll
    for (int m = 0; m < 2; ++m) {
        const int cobase = wco * 32 + m * 16 + (lane >> 2);
        const float b0 = bias[cobase], b1 = bias[cobase + 8];
        #pragma unroll
        for (int j = 0; j < 8; ++j) {
            const int gp = r0 * 32 + wpx * 64 + j * 8 + (lane & 3) * 2;
            float v0 = acc[m][j][0] + b0, v1 = acc[m][j][1] + b0;
            float v2 = acc[m][j][2] + b1, v3 = acc[m][j][3] + b1;
            if (RELU) {
                v0 = fmaxf(v0, 0.f); v1 = fmaxf(v1, 0.f);
                v2 = fmaxf(v2, 0.f); v3 = fmaxf(v3, 0.f);
            }
            size_t o = ((size_t)img * CC + cobase) * NPIX + gp;
            if (RES) { v0 += res[o]; v1 += res[o + 1]; }
            out[o] = v0; out[o + 1] = v1;
            size_t o2 = ((size_t)img * CC + cobase + 8) * NPIX + gp;
            if (RES) { v2 += res[o2]; v3 += res[o2 + 1]; }
            out[o2] = v2; out[o2 + 1] = v3;
        }
    }
}

// ============================================================
// kv conv (block-diagonal): 9 iterations over shifts only.
// B = full-channel per pixel (512B), staged ONCE, XOR-16B row swizzle.
// A prefetch at DISTANCE 1 into the opposite buffer of a 2-ring
// (race-free: write (sh+1)&1 while reading sh&1, wait+sync each iter).
// ============================================================
__global__ __launch_bounds__(512, 1)
void conv_kv_kernel(const __nv_bfloat16* __restrict__ Y,
                    const __nv_bfloat16* __restrict__ Wc,
                    const float* __restrict__ bias,
                    float* __restrict__ out)
{
    extern __shared__ __align__(16) char smem[];
    const uint32_t sb = (uint32_t)__cvta_generic_to_shared(smem);
    const int tid  = threadIdx.x;
    const int lane = tid & 31;
    const int w    = tid >> 5;
    const int wco  = w >> 2;            // 0..3 = co stripe AND its diagonal chunk
    const int wpx  = w & 3;
    const int img  = blockIdx.x >> 2;
    const int r0   = (blockIdx.x & 3) * 8;

    const int arow  = (lane & 7) + ((lane >> 3) & 1) * 8;
    const int akoff = (lane >> 4) * 16;
    const int bjj   = lane >> 4;
    const int khalf = (lane >> 3) & 1;
    const int brow  = lane & 7;

    const char* Yb = (const char*)Y;
    const char* Wb = (const char*)Wc;

    // ---- stage full-channel B once (340 pixel rows x 512B, swizzled) ----
    {
        const size_t ybase = (size_t)img * 1156 * 512;
        for (int i = tid; i < 340 * 32; i += 512) {
            int row = i >> 5, slot = i & 31;
            int hr = row / 34, hc = row - hr * 34;
            cp16(smem + row * 512 + ((slot ^ (row & 7)) << 4),
                 Yb + ybase + ((size_t)(r0 + hr) * 34 + hc) * 512 + slot * 16);
        }
    }
    // ---- diagonal A stage for one shift: rows s=0..127, chunk = s>>5 ----
    auto stage_A = [&](int sh) {
        char* dst = smem + KVA_OFF + (sh & 1) * WBUF;
        #pragma unroll
        for (int k2 = 0; k2 < 3; ++k2) {
            int i = k2 * 512 + tid;
            if (i < 1024) {
                int s = i >> 3, c16 = i & 7;
                const char* src = Wb + (size_t)(sh * 4 + (s >> 5)) * (WPERSHCH * 2);
                cp16(dst + s * 144 + c16 * 16, src + s * 128 + c16 * 16);
            } else {
                int j = i - 1024;
                int s = j >> 2, c16 = j & 3;
                const char* src = Wb + (size_t)(sh * 4 + (s >> 5)) * (WPERSHCH * 2);
                cp16(dst + V1OFF + s * 80 + c16 * 16, src + 16384 + s * 64 + c16 * 16);
            }
        }
    };

    float acc[2][8][4];
    #pragma unroll
    for (int m = 0; m < 2; ++m)
        #pragma unroll
        for (int j = 0; j < 8; ++j)
            #pragma unroll
            for (int q = 0; q < 4; ++q) acc[m][j][q] = 0.f;

    // prologue: B + A(0) must be resident before first compute
    stage_A(0); cp_commit();
    cp_wait0();
    __syncthreads();

    for (int sh = 0; sh < 9; ++sh) {
        // issue next A stage FIRST (into the opposite buffer), then compute
        if (sh + 1 < 9) stage_A(sh + 1);
        cp_commit();

        const int dr = sh / 3, dc = sh - dr * 3;
        uint32_t rb[4]; int s7[4];
        #pragma unroll
        for (int p = 0; p < 4; ++p) {
            int srow = (wpx * 2 + (p >> 1) + dr) * 34
                     + ((p & 1) * 2 + bjj) * 8 + dc + brow;
            rb[p] = sb + srow * 512;
            s7[p] = srow & 7;
        }
        const uint32_t abase = sb + KVA_OFF + (sh & 1) * WBUF;
        const uint32_t aA0 = abase + (wco * 32 + arow) * 144 + akoff;
        const uint32_t aA1 = abase + V1OFF + (wco * 32 + arow) * 80 + akoff;

        #pragma unroll
        for (int ks = 0; ks < 4; ++ks) {
            const int k16 = wco * 8 + ks * 2 + khalf;
            uint32_t bfr[8][2];
            #pragma unroll
            for (int p = 0; p < 4; ++p) {
                uint32_t t4[4];
                ldsm4(t4, rb[p] + ((k16 ^ s7[p]) << 4));
                bfr[2*p][0] = t4[0]; bfr[2*p][1] = t4[1];
                bfr[2*p+1][0] = t4[2]; bfr[2*p+1][1] = t4[3];
            }
            uint32_t a0[4], a1[4];
            ldsm4(a0, aA0 + ks * 32);
            ldsm4(a1, aA0 + 16 * 144 + ks * 32);
            #pragma unroll
            for (int j = 0; j < 8; ++j) {
                mma16816(acc[0][j], a0, bfr[j]);
                mma16816(acc[1][j], a1, bfr[j]);
            }
            if (ks < 2) {
                uint32_t c0[4], c1[4];
                ldsm4(c0, aA1 + ks * 32);
                ldsm4(c1, aA1 + 16 * 80 + ks * 32);
                #pragma unroll
                for (int j = 0; j < 8; ++j) {
                    mma16816(acc[0][j], c0, bfr[j]);
                    mma16816(acc[1][j], c1, bfr[j]);
                }
            }
        }

        cp_wait0();            // A(sh+1) landed (issued ~full compute ago)
        __syncthreads();
    }

    // ---- epilogue ----
    #pragma unroll
    for (int m = 0; m < 2; ++m) {
        const int cobase = wco * 32 + m * 16 + (lane >> 2);
        const float b0 = bias[cobase], b1 = bias[cobase + 8];
        #pragma unroll
        for (int j = 0; j < 8; ++j) {
            const int gp = r0 * 32 + wpx * 64 + j * 8 + (lane & 3) * 2;
            size_t o = ((size_t)img * CC + cobase) * NPIX + gp;
            out[o]     = acc[m][j][0] + b0;
            out[o + 1] = acc[m][j][1] + b0;
            size_t o2 = ((size_t)img * CC + cobase + 8) * NPIX + gp;
            out[o2]     = acc[m][j][2] + b1;
            out[o2 + 1] = acc[m][j][3] + b1;
        }
    }
}

// ============================================================
// attention-key logits: single-sync, all 32 planes in dynamic smem
// ============================================================
__global__ __launch_bounds__(256)
void ak_kernel(const float* __restrict__ v, const float* __restrict__ attw,
               float* __restrict__ ak)
{
    extern __shared__ float aksm[];          // [32][1156] + [288]
    float* sw = aksm + 32 * 1156;
    const int head = blockIdx.x & 3, bt = blockIdx.x >> 2;
    const int b = bt / TT, t = bt % TT;
    const int tid = threadIdx.x, pr = tid >> 3, pc = (tid & 7) * 4;

    for (int ci = 0; ci < 32; ++ci) {
        const float div  = __expf(-(float)(ci >> 1) * (logf(10000.0f) / 16.0f));
        const float ang  = (float)t * div;
        const float posv = (ci & 1) ? cosf(ang) : sinf(ang);
        const float* pl = v + ((size_t)bt * CC + head * DHH + ci) * NPIX;
        float* sp = aksm + ci * 1156;
        for (int idx = tid; idx < 1156; idx += 256) {
            int r = idx / 34 - 1, c = idx % 34 - 1;
            sp[idx] = (r >= 0 && r < 32 && c >= 0 && c < 32) ? (pl[r*32 + c] + posv) : 0.f;
        }
    }
    for (int i = tid; i < 288; i += 256)
        sw[i] = attw[((head * 64) + 32 + i / 9) * 9 + i % 9];
    __syncthreads();

    float acc[4] = {0.f, 0.f, 0.f, 0.f};
    for (int ci = 0; ci < 32; ++ci) {
        const float* sp = aksm + ci * 1156;
        float nb[3][6];
        #pragma unroll
        for (int r = 0; r < 3; ++r)
            #pragma unroll
            for (int c = 0; c < 6; ++c) nb[r][c] = sp[(pr + r) * 34 + pc + c];
        const float* wp = sw + ci * 9;
        #pragma unroll
        for (int p = 0; p < 4; ++p) {
            float s = acc[p];
            s += wp[0]*nb[0][p] + wp[1]*nb[0][p+1] + wp[2]*nb[0][p+2];
            s += wp[3]*nb[1][p] + wp[4]*nb[1][p+1] + wp[5]*nb[1][p+2];
            s += wp[6]*nb[2][p] + wp[7]*nb[2][p+1] + wp[8]*nb[2][p+2];
            acc[p] = s;
        }
    }
    #pragma unroll
    for (int p = 0; p < 4; ++p)
        ak[(((size_t)(b * NHEAD + head) * TT) + t) * NPIX + pr * 32 + pc + p] = acc[p];
}

// ============================================================
__global__ __launch_bounds__(256)
void softmax_ws_kernel(const float* __restrict__ ak, const float* __restrict__ v,
                       float* __restrict__ ws)
{
    const int chunk = blockIdx.x & 3;
    const int gid   = (blockIdx.x >> 2) * 256 + threadIdx.x;
    const int pix = gid & 1023, head = (gid >> 10) & 3, b = gid >> 12;
    float lg[TT], m = -1e30f;
    #pragma unroll
    for (int t = 0; t < TT; ++t) {
        lg[t] = ak[(((size_t)(b * NHEAD + head) * TT) + t) * NPIX + pix];
        m = fmaxf(m, lg[t]);
    }
    float s = 0.f;
    #pragma unroll
    for (int t = 0; t < TT; ++t) { lg[t] = expf(lg[t] - m); s += lg[t]; }
    const float inv = 1.f / s;
    const int c0 = chunk * 8;
    #pragma unroll
    for (int cc = 0; cc < 8; ++cc) {
        int c = c0 + cc;
        float a = 0.f;
        #pragma unroll
        for (int t = 0; t < TT; ++t)
            a += lg[t] * v[((size_t)(b * TT + t) * CC + head * DHH + c) * NPIX + pix];
        ws[((size_t)b * CC + head * DHH + c) * NPIX + pix] = a * inv;
    }
}

// ============================================================
__global__ __launch_bounds__(256)
void groupnorm_kernel(const float* __restrict__ in, const float* __restrict__ gnw,
                      const float* __restrict__ gnb, float* __restrict__ out)
{
    __shared__ float rs[256], rs2[256];
    const int n = blockIdx.x >> 2, g = blockIdx.x & 3, tid = threadIdx.x;
    const float* p = in + (size_t)n * IMG + (size_t)g * 32 * NPIX;
    float s = 0.f, s2 = 0.f;
    for (int i = tid; i < 32 * NPIX; i += 256) { float x = p[i]; s += x; s2 += x * x; }
    rs[tid] = s; rs2[tid] = s2;
    __syncthreads();
    for (int off = 128; off > 0; off >>= 1) {
        if (tid < off) { rs[tid] += rs[tid + off]; rs2[tid] += rs2[tid + off]; }
        __syncthreads();
    }
    const float mean = rs[0] * (1.f / 32768.f);
    const float var  = rs2[0] * (1.f / 32768.f) - mean * mean;
    const float rstd = rsqrtf(var + 1e-5f);
    float* o = out + (size_t)n * IMG + (size_t)g * 32 * NPIX;
    for (int i = tid; i < 32 * NPIX; i += 256) {
        int c = g * 32 + (i >> 10);
        o[i] = (p[i] - mean) * rstd * gnw[c] + gnb[c];
    }
}

// ============================================================
extern "C" void kernel_launch(void* const* d_in, const int* in_sizes, int n_in,
                              void* d_out, int out_size)
{
    const float* x0   = (const float*)d_in[0];
    // q_w, q_b, att_b cancel exactly in the softmax
    const float* kvw  = (const float*)d_in[3];
    const float* kvb  = (const float*)d_in[4];
    const float* attw = (const float*)d_in[5];
    const float* ff1w = (const float*)d_in[7];
    const float* ff1b = (const float*)d_in[8];
    const float* ff2w = (const float*)d_in[9];
    const float* ff2b = (const float*)d_in[10];
    const float* gnw  = (const float*)d_in[11];
    const float* gnb  = (const float*)d_in[12];

    float *cur, *v, *ak, *ws, *att, *ff1, *ff2;
    __nv_bfloat16 *Y, *Wp;
    cudaGetSymbolAddress((void**)&cur, g_cur);
    cudaGetSymbolAddress((void**)&v,   g_v);
    cudaGetSymbolAddress((void**)&ak,  g_ak);
    cudaGetSymbolAddress((void**)&ws,  g_ws);
    cudaGetSymbolAddress((void**)&att, g_att);
    cudaGetSymbolAddress((void**)&ff1, g_ff1);
    cudaGetSymbolAddress((void**)&ff2, g_ff2);
    cudaGetSymbolAddress((void**)&Y,   g_Y);
    cudaGetSymbolAddress((void**)&Wp,  g_Wp);

    cudaFuncSetAttribute(conv_mma_kernel<true, false>, cudaFuncAttributeMaxDynamicSharedMemorySize, CSMEM);
    cudaFuncSetAttribute(conv_mma_kernel<false,true >, cudaFuncAttributeMaxDynamicSharedMemorySize, CSMEM);
    cudaFuncSetAttribute(conv_kv_kernel, cudaFuncAttributeMaxDynamicSharedMemorySize, KVSMEM);
    cudaFuncSetAttribute(ak_kernel, cudaFuncAttributeMaxDynamicSharedMemorySize, AKSMEM);

    wprep_kernel<<<(WPTOT + 255) / 256, 256>>>(kvw, ff1w, ff2w, Wp);
    yzero_kernel<<<(YTOT / 2 + 255) / 256, 256>>>((unsigned*)Y);

    const float* lin = x0;
    for (int l = 0; l < 5; ++l) {
        prep_kernel<false><<<NT * 32, 256>>>(lin, nullptr, nullptr, Y);
        conv_kv_kernel<<<96, 512, KVSMEM>>>(
            Y, Wp + (size_t)(l * 3 + 0) * WPERCONV, kvb + l * 128, v);
        ak_kernel<<<NT * NHEAD, 256, AKSMEM>>>(v, attw + (size_t)l * 4 * 64 * 9, ak);
        softmax_ws_kernel<<<128, 256>>>(ak, v, ws);
        prep_kernel<true><<<NT * 32, 256>>>(lin, ws, att, Y);
        conv_mma_kernel<true,false><<<96, 512, CSMEM>>>(
            Y, Wp + (size_t)(l * 3 + 1) * WPERCONV, ff1b + l * 128, nullptr, ff1);
        prep_kernel<false><<<NT * 32, 256>>>(ff1, nullptr, nullptr, Y);
        conv_mma_kernel<false,true><<<96, 512, CSMEM>>>(
            Y, Wp + (size_t)(l * 3 + 2) * WPERCONV, ff2b + l * 128, att, ff2);
        float* lout = (l == 4) ? (float*)d_out : cur;
        groupnorm_kernel<<<NT * 4, 256>>>(ff2, gnw + l * 128, gnb + l * 128, lout);
        lin = cur;
    }
}